// round 1
// baseline (speedup 1.0000x reference)
#include <cuda_runtime.h>
#include <cuda_bf16.h>

#define NCLS 10
#define NBINS (NCLS + 1)   // bin 10 = dummy for invalid pixels
#define TPB 256

// Global scratch (allocation-free per harness rules). Re-zeroed every launch
// by zero_kernel so kernel_launch is deterministic under graph replay.
__device__ float g_sum[NCLS];
__device__ float g_cnt[NCLS];

__global__ void zero_kernel() {
    int t = threadIdx.x;
    if (t < NCLS) { g_sum[t] = 0.0f; g_cnt[t] = 0.0f; }
}

// Per-thread privatized class bins in shared memory: bins[class][tid] as
// float2{sum_sqerr, count}. tid-major => lanes hit distinct banks; 64-bit
// accesses, zero atomic contention in the hot loop.
__global__ void __launch_bounds__(TPB) acc_kernel(
    const float4* __restrict__ out4,
    const float4* __restrict__ tgt4,
    const int4*   __restrict__ msk4,
    int n4)
{
    __shared__ float2 bins[NBINS * TPB];
    const int tid = threadIdx.x;

    #pragma unroll
    for (int c = 0; c < NBINS; c++)
        bins[c * TPB + tid] = make_float2(0.0f, 0.0f);
    __syncthreads();

    const int stride = gridDim.x * blockDim.x;
    for (int i = blockIdx.x * blockDim.x + tid; i < n4; i += stride) {
        float4 o = out4[i];
        float4 t = tgt4[i];
        int4   m = msk4[i];

        float d0 = o.x - t.x, d1 = o.y - t.y, d2 = o.z - t.z, d3 = o.w - t.w;
        float s0 = d0 * d0, s1 = d1 * d1, s2 = d2 * d2, s3 = d3 * d3;
        // targets hold exact integers 0..9 as floats
        int c0 = (m.x == 1) ? (int)t.x : NCLS;
        int c1 = (m.y == 1) ? (int)t.y : NCLS;
        int c2 = (m.z == 1) ? (int)t.z : NCLS;
        int c3 = (m.w == 1) ? (int)t.w : NCLS;

        float2* p;
        float2 v;
        p = &bins[c0 * TPB + tid]; v = *p; v.x += s0; v.y += 1.0f; *p = v;
        p = &bins[c1 * TPB + tid]; v = *p; v.x += s1; v.y += 1.0f; *p = v;
        p = &bins[c2 * TPB + tid]; v = *p; v.x += s2; v.y += 1.0f; *p = v;
        p = &bins[c3 * TPB + tid]; v = *p; v.x += s3; v.y += 1.0f; *p = v;
    }
    __syncthreads();

    // Tree-reduce the 256 per-thread bins per class (dummy bin 10 ignored).
    for (int s = TPB / 2; s > 0; s >>= 1) {
        if (tid < s) {
            #pragma unroll
            for (int c = 0; c < NCLS; c++) {
                float2 a = bins[c * TPB + tid];
                float2 b = bins[c * TPB + tid + s];
                bins[c * TPB + tid] = make_float2(a.x + b.x, a.y + b.y);
            }
        }
        __syncthreads();
    }

    if (tid < NCLS) {
        atomicAdd(&g_sum[tid], bins[tid * TPB].x);
        atomicAdd(&g_cnt[tid], bins[tid * TPB].y);
    }
}

// Output layout: [loss(1), loss_each(10), class_n(10)] = 21 floats
__global__ void final_kernel(float* __restrict__ out) {
    int t = threadIdx.x;  // one warp
    float le = 0.0f, n = 0.0f;
    if (t < NCLS) {
        n = g_cnt[t];
        le = (n > 0.0f) ? (g_sum[t] / fmaxf(n, 1.0f)) : 0.0f;
        out[1 + t]        = le;
        out[1 + NCLS + t] = n;
    }
    float w = 0.1f * le;
    #pragma unroll
    for (int s = 16; s > 0; s >>= 1)
        w += __shfl_down_sync(0xffffffffu, w, s);
    if (t == 0) out[0] = w;
}

extern "C" void kernel_launch(void* const* d_in, const int* in_sizes, int n_in,
                              void* d_out, int out_size) {
    const float4* o4 = (const float4*)d_in[0];
    const float4* t4 = (const float4*)d_in[1];
    const int4*   m4 = (const int4*)d_in[2];
    float* out = (float*)d_out;

    int n  = in_sizes[0];      // 16,777,216 — divisible by 4
    int n4 = n >> 2;

    int blocks = 148 * 8;      // ~8 CTAs/SM, grid-stride covers the rest
    int maxb = (n4 + TPB - 1) / TPB;
    if (blocks > maxb) blocks = maxb;

    zero_kernel<<<1, 32>>>();
    acc_kernel<<<blocks, TPB>>>(o4, t4, m4, n4);
    final_kernel<<<1, 32>>>(out);
}